// round 12
// baseline (speedup 1.0000x reference)
#include <cuda_runtime.h>
#include <math.h>

#define NN 50000
#define NE 800000
#define NB 32
#define NA 128
#define DEG_CAP 96

// ---- static device scratch (no allocation; zero-initialized at load) ----
__device__ int    g_deg[NN];
__device__ float4 g_edata[NN * DEG_CAP];   // per-slot {vx, vy, vz, cj[dst]}
__device__ float  g_cj[NN];
__device__ float  g_msgin[NN * NB];

__device__ __forceinline__ float coeff_const() {
    constexpr float WF  = 10.0f / 31.0f;
    constexpr float W2F = WF * WF;
    constexpr double C  = -0.5 / (double)W2F;
    return (float)C;
}
// coeff * log2(e), for direct ex2 evaluation: exp(C*x) = ex2(C2*x)
__device__ __forceinline__ float coeff2_const() {
    constexpr float WF  = 10.0f / 31.0f;
    constexpr float W2F = WF * WF;
    constexpr double C  = -0.5 / (double)W2F;
    return (float)(C * 1.4426950408889634);
}
__device__ __forceinline__ float width_const() {
    return 10.0f / 31.0f;
}
__device__ __forceinline__ float ex2f(float x) {
    float r;
    asm("ex2.approx.f32 %0, %1;" : "=f"(r) : "f"(x));
    return r;
}
__device__ __forceinline__ float tanh_approx(float x) {
    float r;
    asm("tanh.approx.f32 %0, %1;" : "=f"(r) : "f"(x));
    return r;
}
__device__ __forceinline__ float silu_tanh(float x) {
    float h = 0.5f * x;
    float t = tanh_approx(h);
    return fmaf(h, t, h);
}

// ---------------------------------------------------------------------------
// cj MLP: 32 nodes/block, 256 threads, warp handles 4 nodes. (R11 exact)
__global__ __launch_bounds__(256)
void cj_kernel5(const float* __restrict__ feat,
                const float* __restrict__ w1,
                const float* __restrict__ b1,
                const float* __restrict__ w2,
                const float* __restrict__ b2,
                int nNodes)
{
    __shared__ float sfeat[32 * NA];   // 16 KB
    const int tid  = threadIdx.x;
    const int warp = tid >> 5;
    const int lane = tid & 31;
    const int node0 = blockIdx.x * 32;

    {
        float4* s4 = (float4*)sfeat;
        const float4* f4 = (const float4*)feat;
        for (int i = tid; i < 32 * (NA / 4); i += 256) {
            int n = node0 + i / (NA / 4);
            float4 v = make_float4(0.f, 0.f, 0.f, 0.f);
            if (n < nNodes) v = __ldg(&f4[(size_t)n * (NA / 4) + (i % (NA / 4))]);
            s4[i] = v;
        }
    }
    __syncthreads();

    const int c4 = lane * 4;
    float acc[4][4];
    #pragma unroll
    for (int i = 0; i < 4; i++)
        #pragma unroll
        for (int j = 0; j < 4; j++) acc[i][j] = 0.0f;

    const float* frow = &sfeat[warp * 4 * NA];
    #pragma unroll 2
    for (int k = 0; k < NA; k += 4) {
        float4 wr0 = __ldg((const float4*)(w1 + (k + 0) * NA + c4));
        float4 wr1 = __ldg((const float4*)(w1 + (k + 1) * NA + c4));
        float4 wr2 = __ldg((const float4*)(w1 + (k + 2) * NA + c4));
        float4 wr3 = __ldg((const float4*)(w1 + (k + 3) * NA + c4));
        #pragma unroll
        for (int i = 0; i < 4; i++) {
            float4 f = *(const float4*)(frow + i * NA + k);
            acc[i][0] = fmaf(f.x, wr0.x, acc[i][0]);
            acc[i][1] = fmaf(f.x, wr0.y, acc[i][1]);
            acc[i][2] = fmaf(f.x, wr0.z, acc[i][2]);
            acc[i][3] = fmaf(f.x, wr0.w, acc[i][3]);
            acc[i][0] = fmaf(f.y, wr1.x, acc[i][0]);
            acc[i][1] = fmaf(f.y, wr1.y, acc[i][1]);
            acc[i][2] = fmaf(f.y, wr1.z, acc[i][2]);
            acc[i][3] = fmaf(f.y, wr1.w, acc[i][3]);
            acc[i][0] = fmaf(f.z, wr2.x, acc[i][0]);
            acc[i][1] = fmaf(f.z, wr2.y, acc[i][1]);
            acc[i][2] = fmaf(f.z, wr2.z, acc[i][2]);
            acc[i][3] = fmaf(f.z, wr2.w, acc[i][3]);
            acc[i][0] = fmaf(f.w, wr3.x, acc[i][0]);
            acc[i][1] = fmaf(f.w, wr3.y, acc[i][1]);
            acc[i][2] = fmaf(f.w, wr3.z, acc[i][2]);
            acc[i][3] = fmaf(f.w, wr3.w, acc[i][3]);
        }
    }

    float4 b1v = __ldg((const float4*)(b1 + c4));
    float4 w2v = __ldg((const float4*)(w2 + c4));
    float p[4];
    #pragma unroll
    for (int i = 0; i < 4; i++) {
        float h0 = silu_tanh(acc[i][0] + b1v.x);
        float h1 = silu_tanh(acc[i][1] + b1v.y);
        float h2 = silu_tanh(acc[i][2] + b1v.z);
        float h3 = silu_tanh(acc[i][3] + b1v.w);
        p[i] = h0 * w2v.x + h1 * w2v.y + h2 * w2v.z + h3 * w2v.w;
    }
    #pragma unroll
    for (int i = 0; i < 4; i++) {
        #pragma unroll
        for (int off = 16; off > 0; off >>= 1)
            p[i] += __shfl_xor_sync(0xffffffffu, p[i], off);
    }
    if (lane == 0) {
        float bb = __ldg(b2);
        #pragma unroll
        for (int i = 0; i < 4; i++) {
            int n = node0 + warp * 4 + i;
            if (n < nNodes) g_cj[n] = p[i] + bb;
        }
    }
}

// ---------------------------------------------------------------------------
// Windowed filt + scatter + staging. Each warp = 2 edges; 16 lanes per edge
// cover the gaussian window [base, base+16). Complement outputs = bias.
__global__ __launch_bounds__(256)
void filt_scatter_kernel(const float* __restrict__ dis_vec,
                         const int*   __restrict__ src,
                         const int*   __restrict__ dst,
                         const float* __restrict__ fw1,
                         const float* __restrict__ fw2,
                         const float* __restrict__ fb2,
                         float* __restrict__ filt_out,
                         int nEdges)
{
    __shared__ float sW1[36];
    __shared__ float sW2[6];
    __shared__ float sB2;

    const int tid = threadIdx.x;
    if (tid < 36) {
        int t = tid / 6;
        float scale = (t == 1 || t == 3 || t == 4) ? 1.41421356237309515f : 1.0f;
        sW1[tid] = fw1[tid] * scale;
    }
    if (tid < 6)  sW2[tid] = fw2[tid];
    if (tid == 36) sB2 = fb2[0];
    __syncthreads();

    const int gwarp = (blockIdx.x * blockDim.x + tid) >> 5;
    const int half  = (tid >> 4) & 1;
    const int sl    = tid & 15;
    const int e     = gwarp * 2 + half;
    if (e >= nEdges) return;

    const float vx = __ldg(&dis_vec[3 * e + 0]);
    const float vy = __ldg(&dis_vec[3 * e + 1]);
    const float vz = __ldg(&dis_vec[3 * e + 2]);

    if (sl == 0) {
        int s = __ldg(&src[e]);
        int pos = atomicAdd(&g_deg[s], 1);
        if (pos < DEG_CAP) {
            float c = __ldg(&g_cj[__ldg(&dst[e])]);
            g_edata[s * DEG_CAP + pos] = make_float4(vx, vy, vz, c);
        }
    }

    const float x = vx + 1e-8f, y = vy + 1e-8f, z = vz + 1e-8f;
    const float xx = x * x, yy = y * y, zz = z * z;
    const float yz = y * z, xz = x * z, xy = x * y;
    const float s2 = xx + yy + zz;

    const float dx = vx + 1e-9f, dy = vy + 1e-9f, dz = vz + 1e-9f;
    float d2 = fmaf(dx, dx, fmaf(dy, dy, dz * dz));
    d2 = fmaxf(d2, 1e-30f);
    const float dis = d2 * __frsqrt_rn(d2);

    const float W = width_const();
    float bf = rintf(dis * (1.0f / W)) - 7.0f;
    bf = fmaxf(0.0f, fminf(16.0f, bf));
    const int   base = (int)bf;
    const int   bidx = base + sl;
    const float off  = (float)bidx * W;
    const float dd   = dis - off;
    const float g0   = ex2f(coeff2_const() * dd * dd);

    const float inv = __fdividef(1.0f, fmaf(g0, s2, 1.0f));
    const float iw2 = 0.5f * inv * g0;

    float r = 0.0f;
    #pragma unroll
    for (int j = 0; j < 6; j++) {
        float p = zz * sW1[0 * 6 + j];
        p = fmaf(yz, sW1[1 * 6 + j], p);
        p = fmaf(yy, sW1[2 * 6 + j], p);
        p = fmaf(xz, sW1[3 * 6 + j], p);
        p = fmaf(xy, sW1[4 * 6 + j], p);
        p = fmaf(xx, sW1[5 * 6 + j], p);
        const float h2 = iw2 * p;
        const float t  = tanh_approx(h2);
        const float sv = fmaf(h2, t, h2);
        r = fmaf(sv, sW2[j], r);
    }
    float* orow = filt_out + (size_t)e * NB;
    orow[bidx] = r + sB2;
    orow[(bidx + 16) & 31] = sB2;
}

// ---------------------------------------------------------------------------
// gather: warp per node; lane = basis. Coalesced float4 staged reads.
// Resets g_deg for the next replay. (R11 structure, ex2-folded exp)
__global__ __launch_bounds__(256)
void gather_kernel(int nNodes)
{
    const int tid  = threadIdx.x;
    const int lane = tid & 31;
    const int node = blockIdx.x * 8 + (tid >> 5);
    if (node >= nNodes) return;

    int deg = g_deg[node];
    if (deg > DEG_CAP) deg = DEG_CAP;
    if (lane == 0) g_deg[node] = 0;
    const float4* edata = &g_edata[node * DEG_CAP];

    const float off = (float)lane * width_const();
    const float C2  = coeff2_const();

    float a0 = 0.f, a1 = 0.f, a2 = 0.f, a3 = 0.f, a4 = 0.f, a5 = 0.f;

    for (int base = 0; base < deg; base += 32) {
        int idx = base + lane;
        float vx = 0.f, vy = 0.f, vz = 0.f, c = 0.f, dis_l = 0.f;
        if (idx < deg) {
            float4 v = edata[idx];
            vx = v.x; vy = v.y; vz = v.z; c = v.w;
            float dxx = vx + 1e-9f, dyy = vy + 1e-9f, dzz = vz + 1e-9f;
            dis_l = sqrtf(fmaf(dxx, dxx, fmaf(dyy, dyy, dzz * dzz)));
        }
        int m = deg - base; if (m > 32) m = 32;
        for (int j = 0; j < m; j++) {
            float bx = __shfl_sync(0xffffffffu, vx, j);
            float by = __shfl_sync(0xffffffffu, vy, j);
            float bz = __shfl_sync(0xffffffffu, vz, j);
            float bc = __shfl_sync(0xffffffffu, c,  j);
            float bd = __shfl_sync(0xffffffffu, dis_l, j);

            float x = bx + 1e-8f, y = by + 1e-8f, z = bz + 1e-8f;
            float dd = bd - off;
            float g0 = ex2f(C2 * dd * dd);
            float w  = g0 * bc;

            a0 = fmaf(z * z, w, a0);
            a1 = fmaf(y * z, w, a1);
            a2 = fmaf(y * y, w, a2);
            a3 = fmaf(x * z, w, a3);
            a4 = fmaf(x * y, w, a4);
            a5 = fmaf(x * x, w, a5);
        }
    }

    float f2 = a0 * a0;
    f2 = fmaf(2.0f * a1, a1, f2);
    f2 = fmaf(a2, a2, f2);
    f2 = fmaf(2.0f * a3, a3, f2);
    f2 = fmaf(2.0f * a4, a4, f2);
    f2 = fmaf(a5, a5, f2);

    float u = f2 + 1e-9f;
    float ss = u * u;
    #pragma unroll
    for (int o = 16; o > 0; o >>= 1)
        ss += __shfl_xor_sync(0xffffffffu, ss, o);
    float invn = __fdividef(1.0f, sqrtf(ss) + 1.0f);
    g_msgin[node * NB + lane] = f2 * invn;
}

// ---------------------------------------------------------------------------
// msg MLP: 64-node tile, NO w1 smem staging (L1-resident __ldg like w2).
// smem 40 KB -> 3 blocks/SM (regs-bound), 24 warps/SM vs 16 before.
__global__ __launch_bounds__(256)
void msg_kernel6(const float* __restrict__ w1,
                 const float* __restrict__ b1,
                 const float* __restrict__ w2,
                 const float* __restrict__ b2,
                 float* __restrict__ out,
                 int nNodes)
{
    extern __shared__ float sm[];
    float* mi  = sm;                 // [64][32]   8 KB
    float* hid = mi + 64 * NB;       // [64][128] 32 KB

    const int tid  = threadIdx.x;
    const int warp = tid >> 5;
    const int lane = tid & 31;
    const int node0 = blockIdx.x * 64;

    for (int i = tid; i < 64 * NB / 4; i += 256) {
        int n = node0 + i / (NB / 4);
        float4 v = make_float4(0.f, 0.f, 0.f, 0.f);
        if (n < nNodes) v = ((const float4*)g_msgin)[(size_t)n * (NB / 4) + (i % (NB / 4))];
        ((float4*)mi)[i] = v;
    }
    __syncthreads();

    const int c4 = lane * 4;
    float acc[8][4];
    #pragma unroll
    for (int i = 0; i < 8; i++)
        #pragma unroll
        for (int j = 0; j < 4; j++) acc[i][j] = 0.0f;

    // Phase A: hidden = silu(mi @ w1 + b1), k = 32, w1 via __ldg
    const float* mrow = &mi[warp * 8 * NB];
    #pragma unroll
    for (int b = 0; b < NB; b += 4) {
        float4 wr0 = __ldg((const float4*)(w1 + (b + 0) * NA + c4));
        float4 wr1 = __ldg((const float4*)(w1 + (b + 1) * NA + c4));
        float4 wr2 = __ldg((const float4*)(w1 + (b + 2) * NA + c4));
        float4 wr3 = __ldg((const float4*)(w1 + (b + 3) * NA + c4));
        #pragma unroll
        for (int i = 0; i < 8; i++) {
            float4 f = *(const float4*)(mrow + i * NB + b);
            acc[i][0] = fmaf(f.x, wr0.x, acc[i][0]);
            acc[i][1] = fmaf(f.x, wr0.y, acc[i][1]);
            acc[i][2] = fmaf(f.x, wr0.z, acc[i][2]);
            acc[i][3] = fmaf(f.x, wr0.w, acc[i][3]);
            acc[i][0] = fmaf(f.y, wr1.x, acc[i][0]);
            acc[i][1] = fmaf(f.y, wr1.y, acc[i][1]);
            acc[i][2] = fmaf(f.y, wr1.z, acc[i][2]);
            acc[i][3] = fmaf(f.y, wr1.w, acc[i][3]);
            acc[i][0] = fmaf(f.z, wr2.x, acc[i][0]);
            acc[i][1] = fmaf(f.z, wr2.y, acc[i][1]);
            acc[i][2] = fmaf(f.z, wr2.z, acc[i][2]);
            acc[i][3] = fmaf(f.z, wr2.w, acc[i][3]);
            acc[i][0] = fmaf(f.w, wr3.x, acc[i][0]);
            acc[i][1] = fmaf(f.w, wr3.y, acc[i][1]);
            acc[i][2] = fmaf(f.w, wr3.z, acc[i][2]);
            acc[i][3] = fmaf(f.w, wr3.w, acc[i][3]);
        }
    }
    {
        float4 b1v = __ldg((const float4*)(b1 + c4));
        #pragma unroll
        for (int i = 0; i < 8; i++) {
            float4 h;
            h.x = silu_tanh(acc[i][0] + b1v.x);
            h.y = silu_tanh(acc[i][1] + b1v.y);
            h.z = silu_tanh(acc[i][2] + b1v.z);
            h.w = silu_tanh(acc[i][3] + b1v.w);
            *(float4*)(hid + (warp * 8 + i) * NA + c4) = h;
        }
    }
    __syncthreads();

    // Phase B: out = hidden @ w2 + b2, k = 128
    #pragma unroll
    for (int i = 0; i < 8; i++)
        #pragma unroll
        for (int j = 0; j < 4; j++) acc[i][j] = 0.0f;

    const float* hrow = &hid[warp * 8 * NA];
    #pragma unroll 2
    for (int k = 0; k < NA; k += 4) {
        float4 wr0 = __ldg((const float4*)(w2 + (k + 0) * NA + c4));
        float4 wr1 = __ldg((const float4*)(w2 + (k + 1) * NA + c4));
        float4 wr2 = __ldg((const float4*)(w2 + (k + 2) * NA + c4));
        float4 wr3 = __ldg((const float4*)(w2 + (k + 3) * NA + c4));
        #pragma unroll
        for (int i = 0; i < 8; i++) {
            float4 f = *(const float4*)(hrow + i * NA + k);
            acc[i][0] = fmaf(f.x, wr0.x, acc[i][0]);
            acc[i][1] = fmaf(f.x, wr0.y, acc[i][1]);
            acc[i][2] = fmaf(f.x, wr0.z, acc[i][2]);
            acc[i][3] = fmaf(f.x, wr0.w, acc[i][3]);
            acc[i][0] = fmaf(f.y, wr1.x, acc[i][0]);
            acc[i][1] = fmaf(f.y, wr1.y, acc[i][1]);
            acc[i][2] = fmaf(f.y, wr1.z, acc[i][2]);
            acc[i][3] = fmaf(f.y, wr1.w, acc[i][3]);
            acc[i][0] = fmaf(f.z, wr2.x, acc[i][0]);
            acc[i][1] = fmaf(f.z, wr2.y, acc[i][1]);
            acc[i][2] = fmaf(f.z, wr2.z, acc[i][2]);
            acc[i][3] = fmaf(f.z, wr2.w, acc[i][3]);
            acc[i][0] = fmaf(f.w, wr3.x, acc[i][0]);
            acc[i][1] = fmaf(f.w, wr3.y, acc[i][1]);
            acc[i][2] = fmaf(f.w, wr3.z, acc[i][2]);
            acc[i][3] = fmaf(f.w, wr3.w, acc[i][3]);
        }
    }
    float4 b2v = __ldg((const float4*)(b2 + c4));
    #pragma unroll
    for (int i = 0; i < 8; i++) {
        int n = node0 + warp * 8 + i;
        if (n < nNodes) {
            float4 o;
            o.x = acc[i][0] + b2v.x;
            o.y = acc[i][1] + b2v.y;
            o.z = acc[i][2] + b2v.z;
            o.w = acc[i][3] + b2v.w;
            *(float4*)(out + (size_t)n * NA + c4) = o;
        }
    }
}

// ---------------------------------------------------------------------------
extern "C" void kernel_launch(void* const* d_in, const int* in_sizes, int n_in,
                              void* d_out, int out_size)
{
    const float* feat    = (const float*)d_in[0];
    const float* dis_vec = (const float*)d_in[1];
    const float* cj_w1   = (const float*)d_in[2];
    const float* cj_b1   = (const float*)d_in[3];
    const float* cj_w2   = (const float*)d_in[4];
    const float* cj_b2   = (const float*)d_in[5];
    const float* msg_w1  = (const float*)d_in[6];
    const float* msg_b1  = (const float*)d_in[7];
    const float* msg_w2  = (const float*)d_in[8];
    const float* msg_b2  = (const float*)d_in[9];
    const float* filt_w1 = (const float*)d_in[10];
    const float* filt_w2 = (const float*)d_in[11];
    const float* filt_b2 = (const float*)d_in[12];
    const int*   src     = (const int*)d_in[13];
    const int*   dst     = (const int*)d_in[14];

    const int nNodes = in_sizes[0] / NA;
    const int nEdges = in_sizes[1] / 3;

    float* out_msg  = (float*)d_out;
    float* out_filt = (float*)d_out + (size_t)nNodes * NA;

    const int msg_smem = (64 * NB + 64 * NA) * sizeof(float);  // 40 KB
    cudaFuncSetAttribute(msg_kernel6, cudaFuncAttributeMaxDynamicSharedMemorySize, msg_smem);

    // 1) cj MLP
    cj_kernel5<<<(nNodes + 31) / 32, 256>>>(feat, cj_w1, cj_b1, cj_w2, cj_b2, nNodes);

    // 2) windowed filt + scatter + staging
    filt_scatter_kernel<<<(nEdges + 15) / 16, 256>>>(dis_vec, src, dst,
                                                     filt_w1, filt_w2, filt_b2,
                                                     out_filt, nEdges);

    // 3) gather (coalesced staged reads; resets g_deg)
    gather_kernel<<<(nNodes + 7) / 8, 256>>>(nNodes);

    // 4) msg MLP (64-node tile, no w1 staging)
    msg_kernel6<<<(nNodes + 63) / 64, 256, msg_smem>>>(msg_w1, msg_b1, msg_w2, msg_b2,
                                                       out_msg, nNodes);
}

// round 13
// speedup vs baseline: 1.0115x; 1.0115x over previous
#include <cuda_runtime.h>
#include <math.h>

#define NN 50000
#define NE 800000
#define NB 32
#define NA 128
#define DEG_CAP 96

// ---- static device scratch (no allocation; zero-initialized at load) ----
__device__ int    g_deg[NN];
__device__ float4 g_edata[NN * DEG_CAP];   // per-slot {vx, vy, vz, cj[dst]}
__device__ float  g_cj[NN];
__device__ float  g_msgin[NN * NB];

// coeff * log2(e), for direct ex2 evaluation: exp(C*x) = ex2(C2*x)
__device__ __forceinline__ float coeff2_const() {
    constexpr float WF  = 10.0f / 31.0f;
    constexpr float W2F = WF * WF;
    constexpr double C  = -0.5 / (double)W2F;
    return (float)(C * 1.4426950408889634);
}
__device__ __forceinline__ float width_const() {
    return 10.0f / 31.0f;
}
__device__ __forceinline__ float ex2f(float x) {
    float r;
    asm("ex2.approx.f32 %0, %1;" : "=f"(r) : "f"(x));
    return r;
}
__device__ __forceinline__ float tanh_approx(float x) {
    float r;
    asm("tanh.approx.f32 %0, %1;" : "=f"(r) : "f"(x));
    return r;
}
__device__ __forceinline__ float silu_tanh(float x) {
    float h = 0.5f * x;
    float t = tanh_approx(h);
    return fmaf(h, t, h);
}

// ---------------------------------------------------------------------------
// cj MLP: 32 nodes/block, 256 threads, warp handles 4 nodes. (R11 exact)
__global__ __launch_bounds__(256)
void cj_kernel5(const float* __restrict__ feat,
                const float* __restrict__ w1,
                const float* __restrict__ b1,
                const float* __restrict__ w2,
                const float* __restrict__ b2,
                int nNodes)
{
    __shared__ float sfeat[32 * NA];   // 16 KB
    const int tid  = threadIdx.x;
    const int warp = tid >> 5;
    const int lane = tid & 31;
    const int node0 = blockIdx.x * 32;

    {
        float4* s4 = (float4*)sfeat;
        const float4* f4 = (const float4*)feat;
        for (int i = tid; i < 32 * (NA / 4); i += 256) {
            int n = node0 + i / (NA / 4);
            float4 v = make_float4(0.f, 0.f, 0.f, 0.f);
            if (n < nNodes) v = __ldg(&f4[(size_t)n * (NA / 4) + (i % (NA / 4))]);
            s4[i] = v;
        }
    }
    __syncthreads();

    const int c4 = lane * 4;
    float acc[4][4];
    #pragma unroll
    for (int i = 0; i < 4; i++)
        #pragma unroll
        for (int j = 0; j < 4; j++) acc[i][j] = 0.0f;

    const float* frow = &sfeat[warp * 4 * NA];
    #pragma unroll 2
    for (int k = 0; k < NA; k += 4) {
        float4 wr0 = __ldg((const float4*)(w1 + (k + 0) * NA + c4));
        float4 wr1 = __ldg((const float4*)(w1 + (k + 1) * NA + c4));
        float4 wr2 = __ldg((const float4*)(w1 + (k + 2) * NA + c4));
        float4 wr3 = __ldg((const float4*)(w1 + (k + 3) * NA + c4));
        #pragma unroll
        for (int i = 0; i < 4; i++) {
            float4 f = *(const float4*)(frow + i * NA + k);
            acc[i][0] = fmaf(f.x, wr0.x, acc[i][0]);
            acc[i][1] = fmaf(f.x, wr0.y, acc[i][1]);
            acc[i][2] = fmaf(f.x, wr0.z, acc[i][2]);
            acc[i][3] = fmaf(f.x, wr0.w, acc[i][3]);
            acc[i][0] = fmaf(f.y, wr1.x, acc[i][0]);
            acc[i][1] = fmaf(f.y, wr1.y, acc[i][1]);
            acc[i][2] = fmaf(f.y, wr1.z, acc[i][2]);
            acc[i][3] = fmaf(f.y, wr1.w, acc[i][3]);
            acc[i][0] = fmaf(f.z, wr2.x, acc[i][0]);
            acc[i][1] = fmaf(f.z, wr2.y, acc[i][1]);
            acc[i][2] = fmaf(f.z, wr2.z, acc[i][2]);
            acc[i][3] = fmaf(f.z, wr2.w, acc[i][3]);
            acc[i][0] = fmaf(f.w, wr3.x, acc[i][0]);
            acc[i][1] = fmaf(f.w, wr3.y, acc[i][1]);
            acc[i][2] = fmaf(f.w, wr3.z, acc[i][2]);
            acc[i][3] = fmaf(f.w, wr3.w, acc[i][3]);
        }
    }

    float4 b1v = __ldg((const float4*)(b1 + c4));
    float4 w2v = __ldg((const float4*)(w2 + c4));
    float p[4];
    #pragma unroll
    for (int i = 0; i < 4; i++) {
        float h0 = silu_tanh(acc[i][0] + b1v.x);
        float h1 = silu_tanh(acc[i][1] + b1v.y);
        float h2 = silu_tanh(acc[i][2] + b1v.z);
        float h3 = silu_tanh(acc[i][3] + b1v.w);
        p[i] = h0 * w2v.x + h1 * w2v.y + h2 * w2v.z + h3 * w2v.w;
    }
    #pragma unroll
    for (int i = 0; i < 4; i++) {
        #pragma unroll
        for (int off = 16; off > 0; off >>= 1)
            p[i] += __shfl_xor_sync(0xffffffffu, p[i], off);
    }
    if (lane == 0) {
        float bb = __ldg(b2);
        #pragma unroll
        for (int i = 0; i < 4; i++) {
            int n = node0 + warp * 4 + i;
            if (n < nNodes) g_cj[n] = p[i] + bb;
        }
    }
}

// ---------------------------------------------------------------------------
// Windowed filt + scatter + staging. Each warp = 2 edges; 16 lanes per edge
// cover the gaussian window [base, base+16). Complement outputs = bias.
__global__ __launch_bounds__(256)
void filt_scatter_kernel(const float* __restrict__ dis_vec,
                         const int*   __restrict__ src,
                         const int*   __restrict__ dst,
                         const float* __restrict__ fw1,
                         const float* __restrict__ fw2,
                         const float* __restrict__ fb2,
                         float* __restrict__ filt_out,
                         int nEdges)
{
    __shared__ float sW1[36];
    __shared__ float sW2[6];
    __shared__ float sB2;

    const int tid = threadIdx.x;
    if (tid < 36) {
        int t = tid / 6;
        float scale = (t == 1 || t == 3 || t == 4) ? 1.41421356237309515f : 1.0f;
        sW1[tid] = fw1[tid] * scale;
    }
    if (tid < 6)  sW2[tid] = fw2[tid];
    if (tid == 36) sB2 = fb2[0];
    __syncthreads();

    const int gwarp = (blockIdx.x * blockDim.x + tid) >> 5;
    const int half  = (tid >> 4) & 1;
    const int sl    = tid & 15;
    const int e     = gwarp * 2 + half;
    if (e >= nEdges) return;

    const float vx = __ldg(&dis_vec[3 * e + 0]);
    const float vy = __ldg(&dis_vec[3 * e + 1]);
    const float vz = __ldg(&dis_vec[3 * e + 2]);

    if (sl == 0) {
        int s = __ldg(&src[e]);
        int pos = atomicAdd(&g_deg[s], 1);
        if (pos < DEG_CAP) {
            float c = __ldg(&g_cj[__ldg(&dst[e])]);
            g_edata[s * DEG_CAP + pos] = make_float4(vx, vy, vz, c);
        }
    }

    const float x = vx + 1e-8f, y = vy + 1e-8f, z = vz + 1e-8f;
    const float xx = x * x, yy = y * y, zz = z * z;
    const float yz = y * z, xz = x * z, xy = x * y;
    const float s2 = xx + yy + zz;

    const float dx = vx + 1e-9f, dy = vy + 1e-9f, dz = vz + 1e-9f;
    float d2 = fmaf(dx, dx, fmaf(dy, dy, dz * dz));
    d2 = fmaxf(d2, 1e-30f);
    const float dis = d2 * __frsqrt_rn(d2);

    const float W = width_const();
    float bf = rintf(dis * (1.0f / W)) - 7.0f;
    bf = fmaxf(0.0f, fminf(16.0f, bf));
    const int   base = (int)bf;
    const int   bidx = base + sl;
    const float off  = (float)bidx * W;
    const float dd   = dis - off;
    const float g0   = ex2f(coeff2_const() * dd * dd);

    const float inv = __fdividef(1.0f, fmaf(g0, s2, 1.0f));
    const float iw2 = 0.5f * inv * g0;

    float r = 0.0f;
    #pragma unroll
    for (int j = 0; j < 6; j++) {
        float p = zz * sW1[0 * 6 + j];
        p = fmaf(yz, sW1[1 * 6 + j], p);
        p = fmaf(yy, sW1[2 * 6 + j], p);
        p = fmaf(xz, sW1[3 * 6 + j], p);
        p = fmaf(xy, sW1[4 * 6 + j], p);
        p = fmaf(xx, sW1[5 * 6 + j], p);
        const float h2 = iw2 * p;
        const float t  = tanh_approx(h2);
        const float sv = fmaf(h2, t, h2);
        r = fmaf(sv, sW2[j], r);
    }
    float* orow = filt_out + (size_t)e * NB;
    orow[bidx] = r + sB2;
    orow[(bidx + 16) & 31] = sB2;
}

// ---------------------------------------------------------------------------
// gather: warp per node; lane = basis. Coalesced float4 staged reads.
// Resets g_deg for the next replay.
__global__ __launch_bounds__(256)
void gather_kernel(int nNodes)
{
    const int tid  = threadIdx.x;
    const int lane = tid & 31;
    const int node = blockIdx.x * 8 + (tid >> 5);
    if (node >= nNodes) return;

    int deg = g_deg[node];
    if (deg > DEG_CAP) deg = DEG_CAP;
    if (lane == 0) g_deg[node] = 0;
    const float4* edata = &g_edata[node * DEG_CAP];

    const float off = (float)lane * width_const();
    const float C2  = coeff2_const();

    float a0 = 0.f, a1 = 0.f, a2 = 0.f, a3 = 0.f, a4 = 0.f, a5 = 0.f;

    for (int base = 0; base < deg; base += 32) {
        int idx = base + lane;
        float vx = 0.f, vy = 0.f, vz = 0.f, c = 0.f, dis_l = 0.f;
        if (idx < deg) {
            float4 v = edata[idx];
            vx = v.x; vy = v.y; vz = v.z; c = v.w;
            float dxx = vx + 1e-9f, dyy = vy + 1e-9f, dzz = vz + 1e-9f;
            dis_l = sqrtf(fmaf(dxx, dxx, fmaf(dyy, dyy, dzz * dzz)));
        }
        int m = deg - base; if (m > 32) m = 32;
        for (int j = 0; j < m; j++) {
            float bx = __shfl_sync(0xffffffffu, vx, j);
            float by = __shfl_sync(0xffffffffu, vy, j);
            float bz = __shfl_sync(0xffffffffu, vz, j);
            float bc = __shfl_sync(0xffffffffu, c,  j);
            float bd = __shfl_sync(0xffffffffu, dis_l, j);

            float x = bx + 1e-8f, y = by + 1e-8f, z = bz + 1e-8f;
            float dd = bd - off;
            float g0 = ex2f(C2 * dd * dd);
            float w  = g0 * bc;

            a0 = fmaf(z * z, w, a0);
            a1 = fmaf(y * z, w, a1);
            a2 = fmaf(y * y, w, a2);
            a3 = fmaf(x * z, w, a3);
            a4 = fmaf(x * y, w, a4);
            a5 = fmaf(x * x, w, a5);
        }
    }

    float f2 = a0 * a0;
    f2 = fmaf(2.0f * a1, a1, f2);
    f2 = fmaf(a2, a2, f2);
    f2 = fmaf(2.0f * a3, a3, f2);
    f2 = fmaf(2.0f * a4, a4, f2);
    f2 = fmaf(a5, a5, f2);

    float u = f2 + 1e-9f;
    float ss = u * u;
    #pragma unroll
    for (int o = 16; o > 0; o >>= 1)
        ss += __shfl_xor_sync(0xffffffffu, ss, o);
    float invn = __fdividef(1.0f, sqrtf(ss) + 1.0f);
    g_msgin[node * NB + lane] = f2 * invn;
}

// ---------------------------------------------------------------------------
// msg MLP: 64-node tile, w1 staged in smem (74-reg config), pinned 3 blocks/SM.
__global__ __launch_bounds__(256, 3)
void msg_kernel4(const float* __restrict__ w1,
                 const float* __restrict__ b1,
                 const float* __restrict__ w2,
                 const float* __restrict__ b2,
                 float* __restrict__ out,
                 int nNodes)
{
    extern __shared__ float sm[];
    float* w1s = sm;                 // [32][128]
    float* mi  = w1s + NB * NA;      // [64][32]
    float* hid = mi + 64 * NB;       // [64][128]

    const int tid  = threadIdx.x;
    const int warp = tid >> 5;
    const int lane = tid & 31;
    const int node0 = blockIdx.x * 64;

    for (int i = tid; i < NB * NA / 4; i += 256)
        ((float4*)w1s)[i] = __ldg(&((const float4*)w1)[i]);
    for (int i = tid; i < 64 * NB / 4; i += 256) {
        int n = node0 + i / (NB / 4);
        float4 v = make_float4(0.f, 0.f, 0.f, 0.f);
        if (n < nNodes) v = ((const float4*)g_msgin)[(size_t)n * (NB / 4) + (i % (NB / 4))];
        ((float4*)mi)[i] = v;
    }
    __syncthreads();

    const int c4 = lane * 4;
    float acc[8][4];
    #pragma unroll
    for (int i = 0; i < 8; i++)
        #pragma unroll
        for (int j = 0; j < 4; j++) acc[i][j] = 0.0f;

    const float* mrow = &mi[warp * 8 * NB];
    #pragma unroll
    for (int b = 0; b < NB; b += 4) {
        float4 wr0 = *(const float4*)(w1s + (b + 0) * NA + c4);
        float4 wr1 = *(const float4*)(w1s + (b + 1) * NA + c4);
        float4 wr2 = *(const float4*)(w1s + (b + 2) * NA + c4);
        float4 wr3 = *(const float4*)(w1s + (b + 3) * NA + c4);
        #pragma unroll
        for (int i = 0; i < 8; i++) {
            float4 f = *(const float4*)(mrow + i * NB + b);
            acc[i][0] = fmaf(f.x, wr0.x, acc[i][0]);
            acc[i][1] = fmaf(f.x, wr0.y, acc[i][1]);
            acc[i][2] = fmaf(f.x, wr0.z, acc[i][2]);
            acc[i][3] = fmaf(f.x, wr0.w, acc[i][3]);
            acc[i][0] = fmaf(f.y, wr1.x, acc[i][0]);
            acc[i][1] = fmaf(f.y, wr1.y, acc[i][1]);
            acc[i][2] = fmaf(f.y, wr1.z, acc[i][2]);
            acc[i][3] = fmaf(f.y, wr1.w, acc[i][3]);
            acc[i][0] = fmaf(f.z, wr2.x, acc[i][0]);
            acc[i][1] = fmaf(f.z, wr2.y, acc[i][1]);
            acc[i][2] = fmaf(f.z, wr2.z, acc[i][2]);
            acc[i][3] = fmaf(f.z, wr2.w, acc[i][3]);
            acc[i][0] = fmaf(f.w, wr3.x, acc[i][0]);
            acc[i][1] = fmaf(f.w, wr3.y, acc[i][1]);
            acc[i][2] = fmaf(f.w, wr3.z, acc[i][2]);
            acc[i][3] = fmaf(f.w, wr3.w, acc[i][3]);
        }
    }
    {
        float4 b1v = __ldg((const float4*)(b1 + c4));
        #pragma unroll
        for (int i = 0; i < 8; i++) {
            float4 h;
            h.x = silu_tanh(acc[i][0] + b1v.x);
            h.y = silu_tanh(acc[i][1] + b1v.y);
            h.z = silu_tanh(acc[i][2] + b1v.z);
            h.w = silu_tanh(acc[i][3] + b1v.w);
            *(float4*)(hid + (warp * 8 + i) * NA + c4) = h;
        }
    }
    __syncthreads();

    #pragma unroll
    for (int i = 0; i < 8; i++)
        #pragma unroll
        for (int j = 0; j < 4; j++) acc[i][j] = 0.0f;

    const float* hrow = &hid[warp * 8 * NA];
    #pragma unroll 2
    for (int k = 0; k < NA; k += 4) {
        float4 wr0 = __ldg((const float4*)(w2 + (k + 0) * NA + c4));
        float4 wr1 = __ldg((const float4*)(w2 + (k + 1) * NA + c4));
        float4 wr2 = __ldg((const float4*)(w2 + (k + 2) * NA + c4));
        float4 wr3 = __ldg((const float4*)(w2 + (k + 3) * NA + c4));
        #pragma unroll
        for (int i = 0; i < 8; i++) {
            float4 f = *(const float4*)(hrow + i * NA + k);
            acc[i][0] = fmaf(f.x, wr0.x, acc[i][0]);
            acc[i][1] = fmaf(f.x, wr0.y, acc[i][1]);
            acc[i][2] = fmaf(f.x, wr0.z, acc[i][2]);
            acc[i][3] = fmaf(f.x, wr0.w, acc[i][3]);
            acc[i][0] = fmaf(f.y, wr1.x, acc[i][0]);
            acc[i][1] = fmaf(f.y, wr1.y, acc[i][1]);
            acc[i][2] = fmaf(f.y, wr1.z, acc[i][2]);
            acc[i][3] = fmaf(f.y, wr1.w, acc[i][3]);
            acc[i][0] = fmaf(f.z, wr2.x, acc[i][0]);
            acc[i][1] = fmaf(f.z, wr2.y, acc[i][1]);
            acc[i][2] = fmaf(f.z, wr2.z, acc[i][2]);
            acc[i][3] = fmaf(f.z, wr2.w, acc[i][3]);
            acc[i][0] = fmaf(f.w, wr3.x, acc[i][0]);
            acc[i][1] = fmaf(f.w, wr3.y, acc[i][1]);
            acc[i][2] = fmaf(f.w, wr3.z, acc[i][2]);
            acc[i][3] = fmaf(f.w, wr3.w, acc[i][3]);
        }
    }
    float4 b2v = __ldg((const float4*)(b2 + c4));
    #pragma unroll
    for (int i = 0; i < 8; i++) {
        int n = node0 + warp * 8 + i;
        if (n < nNodes) {
            float4 o;
            o.x = acc[i][0] + b2v.x;
            o.y = acc[i][1] + b2v.y;
            o.z = acc[i][2] + b2v.z;
            o.w = acc[i][3] + b2v.w;
            *(float4*)(out + (size_t)n * NA + c4) = o;
        }
    }
}

// ---------------------------------------------------------------------------
extern "C" void kernel_launch(void* const* d_in, const int* in_sizes, int n_in,
                              void* d_out, int out_size)
{
    const float* feat    = (const float*)d_in[0];
    const float* dis_vec = (const float*)d_in[1];
    const float* cj_w1   = (const float*)d_in[2];
    const float* cj_b1   = (const float*)d_in[3];
    const float* cj_w2   = (const float*)d_in[4];
    const float* cj_b2   = (const float*)d_in[5];
    const float* msg_w1  = (const float*)d_in[6];
    const float* msg_b1  = (const float*)d_in[7];
    const float* msg_w2  = (const float*)d_in[8];
    const float* msg_b2  = (const float*)d_in[9];
    const float* filt_w1 = (const float*)d_in[10];
    const float* filt_w2 = (const float*)d_in[11];
    const float* filt_b2 = (const float*)d_in[12];
    const int*   src     = (const int*)d_in[13];
    const int*   dst     = (const int*)d_in[14];

    const int nNodes = in_sizes[0] / NA;
    const int nEdges = in_sizes[1] / 3;

    float* out_msg  = (float*)d_out;
    float* out_filt = (float*)d_out + (size_t)nNodes * NA;

    const int msg_smem = (NB * NA + 64 * NB + 64 * NA) * sizeof(float); // 57 KB
    cudaFuncSetAttribute(msg_kernel4, cudaFuncAttributeMaxDynamicSharedMemorySize, msg_smem);

    // 1) cj MLP
    cj_kernel5<<<(nNodes + 31) / 32, 256>>>(feat, cj_w1, cj_b1, cj_w2, cj_b2, nNodes);

    // 2) windowed filt + scatter + staging
    filt_scatter_kernel<<<(nEdges + 15) / 16, 256>>>(dis_vec, src, dst,
                                                     filt_w1, filt_w2, filt_b2,
                                                     out_filt, nEdges);

    // 3) gather (coalesced staged reads; resets g_deg)
    gather_kernel<<<(nNodes + 7) / 8, 256>>>(nNodes);

    // 4) msg MLP (64-node tile, w1 staged, pinned 3 blocks/SM)
    msg_kernel4<<<(nNodes + 63) / 64, 256, msg_smem>>>(msg_w1, msg_b1, msg_w2, msg_b2,
                                                       out_msg, nNodes);
}

// round 14
// speedup vs baseline: 1.1360x; 1.1231x over previous
#include <cuda_runtime.h>
#include <math.h>

#define NN 50000
#define NE 800000
#define NB 32
#define NA 128
#define DEG_CAP 96

// ---- static device scratch (no allocation; zero-initialized at load) ----
__device__ int    g_deg[NN];
__device__ float4 g_edata[NN * DEG_CAP];   // per-slot {vx, vy, vz, cj[dst]}
__device__ float  g_cj[NN];
__device__ float  g_msgin[NN * NB];

// coeff * log2(e), for direct ex2 evaluation: exp(C*x) = ex2(C2*x)
__device__ __forceinline__ float coeff2_const() {
    constexpr float WF  = 10.0f / 31.0f;
    constexpr float W2F = WF * WF;
    constexpr double C  = -0.5 / (double)W2F;
    return (float)(C * 1.4426950408889634);
}
__device__ __forceinline__ float width_const() {
    return 10.0f / 31.0f;
}
__device__ __forceinline__ float ex2f(float x) {
    float r;
    asm("ex2.approx.f32 %0, %1;" : "=f"(r) : "f"(x));
    return r;
}
__device__ __forceinline__ float tanh_approx(float x) {
    float r;
    asm("tanh.approx.f32 %0, %1;" : "=f"(r) : "f"(x));
    return r;
}
__device__ __forceinline__ float silu_tanh(float x) {
    float h = 0.5f * x;
    float t = tanh_approx(h);
    return fmaf(h, t, h);
}

// ---------------------------------------------------------------------------
// cj MLP: 32 nodes/block, 256 threads, warp handles 4 nodes. (R11/R13 exact)
__global__ __launch_bounds__(256)
void cj_kernel5(const float* __restrict__ feat,
                const float* __restrict__ w1,
                const float* __restrict__ b1,
                const float* __restrict__ w2,
                const float* __restrict__ b2,
                int nNodes)
{
    __shared__ float sfeat[32 * NA];   // 16 KB
    const int tid  = threadIdx.x;
    const int warp = tid >> 5;
    const int lane = tid & 31;
    const int node0 = blockIdx.x * 32;

    {
        float4* s4 = (float4*)sfeat;
        const float4* f4 = (const float4*)feat;
        for (int i = tid; i < 32 * (NA / 4); i += 256) {
            int n = node0 + i / (NA / 4);
            float4 v = make_float4(0.f, 0.f, 0.f, 0.f);
            if (n < nNodes) v = __ldg(&f4[(size_t)n * (NA / 4) + (i % (NA / 4))]);
            s4[i] = v;
        }
    }
    __syncthreads();

    const int c4 = lane * 4;
    float acc[4][4];
    #pragma unroll
    for (int i = 0; i < 4; i++)
        #pragma unroll
        for (int j = 0; j < 4; j++) acc[i][j] = 0.0f;

    const float* frow = &sfeat[warp * 4 * NA];
    #pragma unroll 2
    for (int k = 0; k < NA; k += 4) {
        float4 wr0 = __ldg((const float4*)(w1 + (k + 0) * NA + c4));
        float4 wr1 = __ldg((const float4*)(w1 + (k + 1) * NA + c4));
        float4 wr2 = __ldg((const float4*)(w1 + (k + 2) * NA + c4));
        float4 wr3 = __ldg((const float4*)(w1 + (k + 3) * NA + c4));
        #pragma unroll
        for (int i = 0; i < 4; i++) {
            float4 f = *(const float4*)(frow + i * NA + k);
            acc[i][0] = fmaf(f.x, wr0.x, acc[i][0]);
            acc[i][1] = fmaf(f.x, wr0.y, acc[i][1]);
            acc[i][2] = fmaf(f.x, wr0.z, acc[i][2]);
            acc[i][3] = fmaf(f.x, wr0.w, acc[i][3]);
            acc[i][0] = fmaf(f.y, wr1.x, acc[i][0]);
            acc[i][1] = fmaf(f.y, wr1.y, acc[i][1]);
            acc[i][2] = fmaf(f.y, wr1.z, acc[i][2]);
            acc[i][3] = fmaf(f.y, wr1.w, acc[i][3]);
            acc[i][0] = fmaf(f.z, wr2.x, acc[i][0]);
            acc[i][1] = fmaf(f.z, wr2.y, acc[i][1]);
            acc[i][2] = fmaf(f.z, wr2.z, acc[i][2]);
            acc[i][3] = fmaf(f.z, wr2.w, acc[i][3]);
            acc[i][0] = fmaf(f.w, wr3.x, acc[i][0]);
            acc[i][1] = fmaf(f.w, wr3.y, acc[i][1]);
            acc[i][2] = fmaf(f.w, wr3.z, acc[i][2]);
            acc[i][3] = fmaf(f.w, wr3.w, acc[i][3]);
        }
    }

    float4 b1v = __ldg((const float4*)(b1 + c4));
    float4 w2v = __ldg((const float4*)(w2 + c4));
    float p[4];
    #pragma unroll
    for (int i = 0; i < 4; i++) {
        float h0 = silu_tanh(acc[i][0] + b1v.x);
        float h1 = silu_tanh(acc[i][1] + b1v.y);
        float h2 = silu_tanh(acc[i][2] + b1v.z);
        float h3 = silu_tanh(acc[i][3] + b1v.w);
        p[i] = h0 * w2v.x + h1 * w2v.y + h2 * w2v.z + h3 * w2v.w;
    }
    #pragma unroll
    for (int i = 0; i < 4; i++) {
        #pragma unroll
        for (int off = 16; off > 0; off >>= 1)
            p[i] += __shfl_xor_sync(0xffffffffu, p[i], off);
    }
    if (lane == 0) {
        float bb = __ldg(b2);
        #pragma unroll
        for (int i = 0; i < 4; i++) {
            int n = node0 + warp * 4 + i;
            if (n < nNodes) g_cj[n] = p[i] + bb;
        }
    }
}

// ---------------------------------------------------------------------------
// Windowed filt + scatter + staging. Each warp = 2 edges; 16 lanes per edge
// cover the gaussian window [base, base+16). Complement outputs = bias.
// NEW: the 6x6 matvec p_j (lane-invariant per edge) is computed once by
// lanes 0-5 of each half-warp and broadcast via shfl.idx — removes 30 FMA
// + 30 LDS per warp from the hot path. Numerically identical.
__global__ __launch_bounds__(256)
void filt_scatter_kernel(const float* __restrict__ dis_vec,
                         const int*   __restrict__ src,
                         const int*   __restrict__ dst,
                         const float* __restrict__ fw1,
                         const float* __restrict__ fw2,
                         const float* __restrict__ fb2,
                         float* __restrict__ filt_out,
                         int nEdges)
{
    __shared__ float sW1[36];
    __shared__ float sW2[6];
    __shared__ float sB2;

    const int tid = threadIdx.x;
    if (tid < 36) {
        int t = tid / 6;
        float scale = (t == 1 || t == 3 || t == 4) ? 1.41421356237309515f : 1.0f;
        sW1[tid] = fw1[tid] * scale;
    }
    if (tid < 6)  sW2[tid] = fw2[tid];
    if (tid == 36) sB2 = fb2[0];
    __syncthreads();

    const int gwarp = (blockIdx.x * blockDim.x + tid) >> 5;
    const int lane  = tid & 31;
    const int half  = (lane >> 4) & 1;
    const int sl    = lane & 15;
    int e = gwarp * 2 + half;
    const bool valid = (e < nEdges);
    if (!valid) e = nEdges - 1;   // clamp; keep all lanes alive for shuffles

    const float vx = __ldg(&dis_vec[3 * e + 0]);
    const float vy = __ldg(&dis_vec[3 * e + 1]);
    const float vz = __ldg(&dis_vec[3 * e + 2]);

    if (sl == 0 && valid) {
        int s = __ldg(&src[e]);
        int pos = atomicAdd(&g_deg[s], 1);
        if (pos < DEG_CAP) {
            float c = __ldg(&g_cj[__ldg(&dst[e])]);
            g_edata[s * DEG_CAP + pos] = make_float4(vx, vy, vz, c);
        }
    }

    const float x = vx + 1e-8f, y = vy + 1e-8f, z = vz + 1e-8f;
    const float xx = x * x, yy = y * y, zz = z * z;
    const float yz = y * z, xz = x * z, xy = x * y;
    const float s2 = xx + yy + zz;

    const float dx = vx + 1e-9f, dy = vy + 1e-9f, dz = vz + 1e-9f;
    float d2 = fmaf(dx, dx, fmaf(dy, dy, dz * dz));
    d2 = fmaxf(d2, 1e-30f);
    const float dis = d2 * __frsqrt_rn(d2);

    const float W = width_const();
    float bf = rintf(dis * (1.0f / W)) - 7.0f;
    bf = fmaxf(0.0f, fminf(16.0f, bf));
    const int   base = (int)bf;
    const int   bidx = base + sl;
    const float off  = (float)bidx * W;
    const float dd   = dis - off;
    const float g0   = ex2f(coeff2_const() * dd * dd);

    const float inv = __fdividef(1.0f, fmaf(g0, s2, 1.0f));
    const float iw2 = 0.5f * inv * g0;

    // lane sl (<6) computes p_{sl} for its edge; identical across the 16
    // lanes of an edge, so compute once and broadcast.
    float p;
    {
        const int j = (sl < 6) ? sl : 0;
        p = zz * sW1[0 * 6 + j];
        p = fmaf(yz, sW1[1 * 6 + j], p);
        p = fmaf(yy, sW1[2 * 6 + j], p);
        p = fmaf(xz, sW1[3 * 6 + j], p);
        p = fmaf(xy, sW1[4 * 6 + j], p);
        p = fmaf(xx, sW1[5 * 6 + j], p);
    }
    const int baseLane = lane & 16;   // 0 for edge A lanes, 16 for edge B lanes

    float r = 0.0f;
    #pragma unroll
    for (int j = 0; j < 6; j++) {
        const float pj = __shfl_sync(0xffffffffu, p, baseLane + j);
        const float h2 = iw2 * pj;
        const float t  = tanh_approx(h2);
        const float sv = fmaf(h2, t, h2);
        r = fmaf(sv, sW2[j], r);
    }

    if (valid) {
        float* orow = filt_out + (size_t)e * NB;
        orow[bidx] = r + sB2;
        orow[(bidx + 16) & 31] = sB2;
    }
}

// ---------------------------------------------------------------------------
// gather: warp per node; lane = basis. Coalesced float4 staged reads.
// Resets g_deg for the next replay. (R13 exact)
__global__ __launch_bounds__(256)
void gather_kernel(int nNodes)
{
    const int tid  = threadIdx.x;
    const int lane = tid & 31;
    const int node = blockIdx.x * 8 + (tid >> 5);
    if (node >= nNodes) return;

    int deg = g_deg[node];
    if (deg > DEG_CAP) deg = DEG_CAP;
    if (lane == 0) g_deg[node] = 0;
    const float4* edata = &g_edata[node * DEG_CAP];

    const float off = (float)lane * width_const();
    const float C2  = coeff2_const();

    float a0 = 0.f, a1 = 0.f, a2 = 0.f, a3 = 0.f, a4 = 0.f, a5 = 0.f;

    for (int base = 0; base < deg; base += 32) {
        int idx = base + lane;
        float vx = 0.f, vy = 0.f, vz = 0.f, c = 0.f, dis_l = 0.f;
        if (idx < deg) {
            float4 v = edata[idx];
            vx = v.x; vy = v.y; vz = v.z; c = v.w;
            float dxx = vx + 1e-9f, dyy = vy + 1e-9f, dzz = vz + 1e-9f;
            dis_l = sqrtf(fmaf(dxx, dxx, fmaf(dyy, dyy, dzz * dzz)));
        }
        int m = deg - base; if (m > 32) m = 32;
        for (int j = 0; j < m; j++) {
            float bx = __shfl_sync(0xffffffffu, vx, j);
            float by = __shfl_sync(0xffffffffu, vy, j);
            float bz = __shfl_sync(0xffffffffu, vz, j);
            float bc = __shfl_sync(0xffffffffu, c,  j);
            float bd = __shfl_sync(0xffffffffu, dis_l, j);

            float x = bx + 1e-8f, y = by + 1e-8f, z = bz + 1e-8f;
            float dd = bd - off;
            float g0 = ex2f(C2 * dd * dd);
            float w  = g0 * bc;

            a0 = fmaf(z * z, w, a0);
            a1 = fmaf(y * z, w, a1);
            a2 = fmaf(y * y, w, a2);
            a3 = fmaf(x * z, w, a3);
            a4 = fmaf(x * y, w, a4);
            a5 = fmaf(x * x, w, a5);
        }
    }

    float f2 = a0 * a0;
    f2 = fmaf(2.0f * a1, a1, f2);
    f2 = fmaf(a2, a2, f2);
    f2 = fmaf(2.0f * a3, a3, f2);
    f2 = fmaf(2.0f * a4, a4, f2);
    f2 = fmaf(a5, a5, f2);

    float u = f2 + 1e-9f;
    float ss = u * u;
    #pragma unroll
    for (int o = 16; o > 0; o >>= 1)
        ss += __shfl_xor_sync(0xffffffffu, ss, o);
    float invn = __fdividef(1.0f, sqrtf(ss) + 1.0f);
    g_msgin[node * NB + lane] = f2 * invn;
}

// ---------------------------------------------------------------------------
// msg MLP: 64-node tile, w1 staged in smem, pinned 3 blocks/SM. (R13 exact)
__global__ __launch_bounds__(256, 3)
void msg_kernel4(const float* __restrict__ w1,
                 const float* __restrict__ b1,
                 const float* __restrict__ w2,
                 const float* __restrict__ b2,
                 float* __restrict__ out,
                 int nNodes)
{
    extern __shared__ float sm[];
    float* w1s = sm;                 // [32][128]
    float* mi  = w1s + NB * NA;      // [64][32]
    float* hid = mi + 64 * NB;       // [64][128]

    const int tid  = threadIdx.x;
    const int warp = tid >> 5;
    const int lane = tid & 31;
    const int node0 = blockIdx.x * 64;

    for (int i = tid; i < NB * NA / 4; i += 256)
        ((float4*)w1s)[i] = __ldg(&((const float4*)w1)[i]);
    for (int i = tid; i < 64 * NB / 4; i += 256) {
        int n = node0 + i / (NB / 4);
        float4 v = make_float4(0.f, 0.f, 0.f, 0.f);
        if (n < nNodes) v = ((const float4*)g_msgin)[(size_t)n * (NB / 4) + (i % (NB / 4))];
        ((float4*)mi)[i] = v;
    }
    __syncthreads();

    const int c4 = lane * 4;
    float acc[8][4];
    #pragma unroll
    for (int i = 0; i < 8; i++)
        #pragma unroll
        for (int j = 0; j < 4; j++) acc[i][j] = 0.0f;

    const float* mrow = &mi[warp * 8 * NB];
    #pragma unroll
    for (int b = 0; b < NB; b += 4) {
        float4 wr0 = *(const float4*)(w1s + (b + 0) * NA + c4);
        float4 wr1 = *(const float4*)(w1s + (b + 1) * NA + c4);
        float4 wr2 = *(const float4*)(w1s + (b + 2) * NA + c4);
        float4 wr3 = *(const float4*)(w1s + (b + 3) * NA + c4);
        #pragma unroll
        for (int i = 0; i < 8; i++) {
            float4 f = *(const float4*)(mrow + i * NB + b);
            acc[i][0] = fmaf(f.x, wr0.x, acc[i][0]);
            acc[i][1] = fmaf(f.x, wr0.y, acc[i][1]);
            acc[i][2] = fmaf(f.x, wr0.z, acc[i][2]);
            acc[i][3] = fmaf(f.x, wr0.w, acc[i][3]);
            acc[i][0] = fmaf(f.y, wr1.x, acc[i][0]);
            acc[i][1] = fmaf(f.y, wr1.y, acc[i][1]);
            acc[i][2] = fmaf(f.y, wr1.z, acc[i][2]);
            acc[i][3] = fmaf(f.y, wr1.w, acc[i][3]);
            acc[i][0] = fmaf(f.z, wr2.x, acc[i][0]);
            acc[i][1] = fmaf(f.z, wr2.y, acc[i][1]);
            acc[i][2] = fmaf(f.z, wr2.z, acc[i][2]);
            acc[i][3] = fmaf(f.z, wr2.w, acc[i][3]);
            acc[i][0] = fmaf(f.w, wr3.x, acc[i][0]);
            acc[i][1] = fmaf(f.w, wr3.y, acc[i][1]);
            acc[i][2] = fmaf(f.w, wr3.z, acc[i][2]);
            acc[i][3] = fmaf(f.w, wr3.w, acc[i][3]);
        }
    }
    {
        float4 b1v = __ldg((const float4*)(b1 + c4));
        #pragma unroll
        for (int i = 0; i < 8; i++) {
            float4 h;
            h.x = silu_tanh(acc[i][0] + b1v.x);
            h.y = silu_tanh(acc[i][1] + b1v.y);
            h.z = silu_tanh(acc[i][2] + b1v.z);
            h.w = silu_tanh(acc[i][3] + b1v.w);
            *(float4*)(hid + (warp * 8 + i) * NA + c4) = h;
        }
    }
    __syncthreads();

    #pragma unroll
    for (int i = 0; i < 8; i++)
        #pragma unroll
        for (int j = 0; j < 4; j++) acc[i][j] = 0.0f;

    const float* hrow = &hid[warp * 8 * NA];
    #pragma unroll 2
    for (int k = 0; k < NA; k += 4) {
        float4 wr0 = __ldg((const float4*)(w2 + (k + 0) * NA + c4));
        float4 wr1 = __ldg((const float4*)(w2 + (k + 1) * NA + c4));
        float4 wr2 = __ldg((const float4*)(w2 + (k + 2) * NA + c4));
        float4 wr3 = __ldg((const float4*)(w2 + (k + 3) * NA + c4));
        #pragma unroll
        for (int i = 0; i < 8; i++) {
            float4 f = *(const float4*)(hrow + i * NA + k);
            acc[i][0] = fmaf(f.x, wr0.x, acc[i][0]);
            acc[i][1] = fmaf(f.x, wr0.y, acc[i][1]);
            acc[i][2] = fmaf(f.x, wr0.z, acc[i][2]);
            acc[i][3] = fmaf(f.x, wr0.w, acc[i][3]);
            acc[i][0] = fmaf(f.y, wr1.x, acc[i][0]);
            acc[i][1] = fmaf(f.y, wr1.y, acc[i][1]);
            acc[i][2] = fmaf(f.y, wr1.z, acc[i][2]);
            acc[i][3] = fmaf(f.y, wr1.w, acc[i][3]);
            acc[i][0] = fmaf(f.z, wr2.x, acc[i][0]);
            acc[i][1] = fmaf(f.z, wr2.y, acc[i][1]);
            acc[i][2] = fmaf(f.z, wr2.z, acc[i][2]);
            acc[i][3] = fmaf(f.z, wr2.w, acc[i][3]);
            acc[i][0] = fmaf(f.w, wr3.x, acc[i][0]);
            acc[i][1] = fmaf(f.w, wr3.y, acc[i][1]);
            acc[i][2] = fmaf(f.w, wr3.z, acc[i][2]);
            acc[i][3] = fmaf(f.w, wr3.w, acc[i][3]);
        }
    }
    float4 b2v = __ldg((const float4*)(b2 + c4));
    #pragma unroll
    for (int i = 0; i < 8; i++) {
        int n = node0 + warp * 8 + i;
        if (n < nNodes) {
            float4 o;
            o.x = acc[i][0] + b2v.x;
            o.y = acc[i][1] + b2v.y;
            o.z = acc[i][2] + b2v.z;
            o.w = acc[i][3] + b2v.w;
            *(float4*)(out + (size_t)n * NA + c4) = o;
        }
    }
}

// ---------------------------------------------------------------------------
extern "C" void kernel_launch(void* const* d_in, const int* in_sizes, int n_in,
                              void* d_out, int out_size)
{
    const float* feat    = (const float*)d_in[0];
    const float* dis_vec = (const float*)d_in[1];
    const float* cj_w1   = (const float*)d_in[2];
    const float* cj_b1   = (const float*)d_in[3];
    const float* cj_w2   = (const float*)d_in[4];
    const float* cj_b2   = (const float*)d_in[5];
    const float* msg_w1  = (const float*)d_in[6];
    const float* msg_b1  = (const float*)d_in[7];
    const float* msg_w2  = (const float*)d_in[8];
    const float* msg_b2  = (const float*)d_in[9];
    const float* filt_w1 = (const float*)d_in[10];
    const float* filt_w2 = (const float*)d_in[11];
    const float* filt_b2 = (const float*)d_in[12];
    const int*   src     = (const int*)d_in[13];
    const int*   dst     = (const int*)d_in[14];

    const int nNodes = in_sizes[0] / NA;
    const int nEdges = in_sizes[1] / 3;

    float* out_msg  = (float*)d_out;
    float* out_filt = (float*)d_out + (size_t)nNodes * NA;

    const int msg_smem = (NB * NA + 64 * NB + 64 * NA) * sizeof(float); // 57 KB
    cudaFuncSetAttribute(msg_kernel4, cudaFuncAttributeMaxDynamicSharedMemorySize, msg_smem);

    // 1) cj MLP
    cj_kernel5<<<(nNodes + 31) / 32, 256>>>(feat, cj_w1, cj_b1, cj_w2, cj_b2, nNodes);

    // 2) windowed filt + scatter + staging (shared matvec + shuffle broadcast)
    filt_scatter_kernel<<<(nEdges + 15) / 16, 256>>>(dis_vec, src, dst,
                                                     filt_w1, filt_w2, filt_b2,
                                                     out_filt, nEdges);

    // 3) gather (coalesced staged reads; resets g_deg)
    gather_kernel<<<(nNodes + 7) / 8, 256>>>(nNodes);

    // 4) msg MLP (64-node tile, w1 staged, pinned 3 blocks/SM)
    msg_kernel4<<<(nNodes + 63) / 64, 256, msg_smem>>>(msg_w1, msg_b1, msg_w2, msg_b2,
                                                       out_msg, nNodes);
}

// round 15
// speedup vs baseline: 1.1755x; 1.0347x over previous
#include <cuda_runtime.h>
#include <math.h>
#include <stdint.h>

#define NN 50000
#define NE 800000
#define NB 32
#define NA 128
#define HID_LD 132   // padded hid row stride (floats): 4r+tc bank rotation
#define DEG_CAP 96

// ---- static device scratch (no allocation; zero-initialized at load) ----
__device__ int    g_deg[NN];
__device__ float4 g_edata[NN * DEG_CAP];   // per-slot {vx, vy, vz, cj[dst]}
__device__ float  g_cj[NN];
__device__ float  g_msgin[NN * NB];

// coeff * log2(e), for direct ex2 evaluation: exp(C*x) = ex2(C2*x)
__device__ __forceinline__ float coeff2_const() {
    constexpr float WF  = 10.0f / 31.0f;
    constexpr float W2F = WF * WF;
    constexpr double C  = -0.5 / (double)W2F;
    return (float)(C * 1.4426950408889634);
}
__device__ __forceinline__ float width_const() {
    return 10.0f / 31.0f;
}
__device__ __forceinline__ float ex2f(float x) {
    float r;
    asm("ex2.approx.f32 %0, %1;" : "=f"(r) : "f"(x));
    return r;
}
__device__ __forceinline__ float tanh_approx(float x) {
    float r;
    asm("tanh.approx.f32 %0, %1;" : "=f"(r) : "f"(x));
    return r;
}
__device__ __forceinline__ float silu_tanh(float x) {
    float h = 0.5f * x;
    float t = tanh_approx(h);
    return fmaf(h, t, h);
}
__device__ __forceinline__ uint32_t f2tf32(float x) {
    uint32_t r;
    asm("cvt.rna.tf32.f32 %0, %1;" : "=r"(r) : "f"(x));
    return r;
}
__device__ __forceinline__ void mma_tf32(float* d,
    uint32_t a0, uint32_t a1, uint32_t a2, uint32_t a3,
    uint32_t b0, uint32_t b1)
{
    asm volatile(
        "mma.sync.aligned.m16n8k8.row.col.f32.tf32.tf32.f32 "
        "{%0,%1,%2,%3}, {%4,%5,%6,%7}, {%8,%9}, {%0,%1,%2,%3};"
        : "+f"(d[0]), "+f"(d[1]), "+f"(d[2]), "+f"(d[3])
        : "r"(a0), "r"(a1), "r"(a2), "r"(a3), "r"(b0), "r"(b1));
}

// ---------------------------------------------------------------------------
// cj MLP: 32 nodes/block, 256 threads, warp handles 4 nodes. (R14 exact)
__global__ __launch_bounds__(256)
void cj_kernel5(const float* __restrict__ feat,
                const float* __restrict__ w1,
                const float* __restrict__ b1,
                const float* __restrict__ w2,
                const float* __restrict__ b2,
                int nNodes)
{
    __shared__ float sfeat[32 * NA];   // 16 KB
    const int tid  = threadIdx.x;
    const int warp = tid >> 5;
    const int lane = tid & 31;
    const int node0 = blockIdx.x * 32;

    {
        float4* s4 = (float4*)sfeat;
        const float4* f4 = (const float4*)feat;
        for (int i = tid; i < 32 * (NA / 4); i += 256) {
            int n = node0 + i / (NA / 4);
            float4 v = make_float4(0.f, 0.f, 0.f, 0.f);
            if (n < nNodes) v = __ldg(&f4[(size_t)n * (NA / 4) + (i % (NA / 4))]);
            s4[i] = v;
        }
    }
    __syncthreads();

    const int c4 = lane * 4;
    float acc[4][4];
    #pragma unroll
    for (int i = 0; i < 4; i++)
        #pragma unroll
        for (int j = 0; j < 4; j++) acc[i][j] = 0.0f;

    const float* frow = &sfeat[warp * 4 * NA];
    #pragma unroll 2
    for (int k = 0; k < NA; k += 4) {
        float4 wr0 = __ldg((const float4*)(w1 + (k + 0) * NA + c4));
        float4 wr1 = __ldg((const float4*)(w1 + (k + 1) * NA + c4));
        float4 wr2 = __ldg((const float4*)(w1 + (k + 2) * NA + c4));
        float4 wr3 = __ldg((const float4*)(w1 + (k + 3) * NA + c4));
        #pragma unroll
        for (int i = 0; i < 4; i++) {
            float4 f = *(const float4*)(frow + i * NA + k);
            acc[i][0] = fmaf(f.x, wr0.x, acc[i][0]);
            acc[i][1] = fmaf(f.x, wr0.y, acc[i][1]);
            acc[i][2] = fmaf(f.x, wr0.z, acc[i][2]);
            acc[i][3] = fmaf(f.x, wr0.w, acc[i][3]);
            acc[i][0] = fmaf(f.y, wr1.x, acc[i][0]);
            acc[i][1] = fmaf(f.y, wr1.y, acc[i][1]);
            acc[i][2] = fmaf(f.y, wr1.z, acc[i][2]);
            acc[i][3] = fmaf(f.y, wr1.w, acc[i][3]);
            acc[i][0] = fmaf(f.z, wr2.x, acc[i][0]);
            acc[i][1] = fmaf(f.z, wr2.y, acc[i][1]);
            acc[i][2] = fmaf(f.z, wr2.z, acc[i][2]);
            acc[i][3] = fmaf(f.z, wr2.w, acc[i][3]);
            acc[i][0] = fmaf(f.w, wr3.x, acc[i][0]);
            acc[i][1] = fmaf(f.w, wr3.y, acc[i][1]);
            acc[i][2] = fmaf(f.w, wr3.z, acc[i][2]);
            acc[i][3] = fmaf(f.w, wr3.w, acc[i][3]);
        }
    }

    float4 b1v = __ldg((const float4*)(b1 + c4));
    float4 w2v = __ldg((const float4*)(w2 + c4));
    float p[4];
    #pragma unroll
    for (int i = 0; i < 4; i++) {
        float h0 = silu_tanh(acc[i][0] + b1v.x);
        float h1 = silu_tanh(acc[i][1] + b1v.y);
        float h2 = silu_tanh(acc[i][2] + b1v.z);
        float h3 = silu_tanh(acc[i][3] + b1v.w);
        p[i] = h0 * w2v.x + h1 * w2v.y + h2 * w2v.z + h3 * w2v.w;
    }
    #pragma unroll
    for (int i = 0; i < 4; i++) {
        #pragma unroll
        for (int off = 16; off > 0; off >>= 1)
            p[i] += __shfl_xor_sync(0xffffffffu, p[i], off);
    }
    if (lane == 0) {
        float bb = __ldg(b2);
        #pragma unroll
        for (int i = 0; i < 4; i++) {
            int n = node0 + warp * 4 + i;
            if (n < nNodes) g_cj[n] = p[i] + bb;
        }
    }
}

// ---------------------------------------------------------------------------
// Windowed filt + scatter + staging with shared matvec broadcast. (R14 exact)
__global__ __launch_bounds__(256)
void filt_scatter_kernel(const float* __restrict__ dis_vec,
                         const int*   __restrict__ src,
                         const int*   __restrict__ dst,
                         const float* __restrict__ fw1,
                         const float* __restrict__ fw2,
                         const float* __restrict__ fb2,
                         float* __restrict__ filt_out,
                         int nEdges)
{
    __shared__ float sW1[36];
    __shared__ float sW2[6];
    __shared__ float sB2;

    const int tid = threadIdx.x;
    if (tid < 36) {
        int t = tid / 6;
        float scale = (t == 1 || t == 3 || t == 4) ? 1.41421356237309515f : 1.0f;
        sW1[tid] = fw1[tid] * scale;
    }
    if (tid < 6)  sW2[tid] = fw2[tid];
    if (tid == 36) sB2 = fb2[0];
    __syncthreads();

    const int gwarp = (blockIdx.x * blockDim.x + tid) >> 5;
    const int lane  = tid & 31;
    const int half  = (lane >> 4) & 1;
    const int sl    = lane & 15;
    int e = gwarp * 2 + half;
    const bool valid = (e < nEdges);
    if (!valid) e = nEdges - 1;

    const float vx = __ldg(&dis_vec[3 * e + 0]);
    const float vy = __ldg(&dis_vec[3 * e + 1]);
    const float vz = __ldg(&dis_vec[3 * e + 2]);

    if (sl == 0 && valid) {
        int s = __ldg(&src[e]);
        int pos = atomicAdd(&g_deg[s], 1);
        if (pos < DEG_CAP) {
            float c = __ldg(&g_cj[__ldg(&dst[e])]);
            g_edata[s * DEG_CAP + pos] = make_float4(vx, vy, vz, c);
        }
    }

    const float x = vx + 1e-8f, y = vy + 1e-8f, z = vz + 1e-8f;
    const float xx = x * x, yy = y * y, zz = z * z;
    const float yz = y * z, xz = x * z, xy = x * y;
    const float s2 = xx + yy + zz;

    const float dx = vx + 1e-9f, dy = vy + 1e-9f, dz = vz + 1e-9f;
    float d2 = fmaf(dx, dx, fmaf(dy, dy, dz * dz));
    d2 = fmaxf(d2, 1e-30f);
    const float dis = d2 * __frsqrt_rn(d2);

    const float W = width_const();
    float bf = rintf(dis * (1.0f / W)) - 7.0f;
    bf = fmaxf(0.0f, fminf(16.0f, bf));
    const int   base = (int)bf;
    const int   bidx = base + sl;
    const float off  = (float)bidx * W;
    const float dd   = dis - off;
    const float g0   = ex2f(coeff2_const() * dd * dd);

    const float inv = __fdividef(1.0f, fmaf(g0, s2, 1.0f));
    const float iw2 = 0.5f * inv * g0;

    float p;
    {
        const int j = (sl < 6) ? sl : 0;
        p = zz * sW1[0 * 6 + j];
        p = fmaf(yz, sW1[1 * 6 + j], p);
        p = fmaf(yy, sW1[2 * 6 + j], p);
        p = fmaf(xz, sW1[3 * 6 + j], p);
        p = fmaf(xy, sW1[4 * 6 + j], p);
        p = fmaf(xx, sW1[5 * 6 + j], p);
    }
    const int baseLane = lane & 16;

    float r = 0.0f;
    #pragma unroll
    for (int j = 0; j < 6; j++) {
        const float pj = __shfl_sync(0xffffffffu, p, baseLane + j);
        const float h2 = iw2 * pj;
        const float t  = tanh_approx(h2);
        const float sv = fmaf(h2, t, h2);
        r = fmaf(sv, sW2[j], r);
    }

    if (valid) {
        float* orow = filt_out + (size_t)e * NB;
        orow[bidx] = r + sB2;
        orow[(bidx + 16) & 31] = sB2;
    }
}

// ---------------------------------------------------------------------------
// gather: warp per node; lane = basis. (R14 exact)
__global__ __launch_bounds__(256)
void gather_kernel(int nNodes)
{
    const int tid  = threadIdx.x;
    const int lane = tid & 31;
    const int node = blockIdx.x * 8 + (tid >> 5);
    if (node >= nNodes) return;

    int deg = g_deg[node];
    if (deg > DEG_CAP) deg = DEG_CAP;
    if (lane == 0) g_deg[node] = 0;
    const float4* edata = &g_edata[node * DEG_CAP];

    const float off = (float)lane * width_const();
    const float C2  = coeff2_const();

    float a0 = 0.f, a1 = 0.f, a2 = 0.f, a3 = 0.f, a4 = 0.f, a5 = 0.f;

    for (int base = 0; base < deg; base += 32) {
        int idx = base + lane;
        float vx = 0.f, vy = 0.f, vz = 0.f, c = 0.f, dis_l = 0.f;
        if (idx < deg) {
            float4 v = edata[idx];
            vx = v.x; vy = v.y; vz = v.z; c = v.w;
            float dxx = vx + 1e-9f, dyy = vy + 1e-9f, dzz = vz + 1e-9f;
            dis_l = sqrtf(fmaf(dxx, dxx, fmaf(dyy, dyy, dzz * dzz)));
        }
        int m = deg - base; if (m > 32) m = 32;
        for (int j = 0; j < m; j++) {
            float bx = __shfl_sync(0xffffffffu, vx, j);
            float by = __shfl_sync(0xffffffffu, vy, j);
            float bz = __shfl_sync(0xffffffffu, vz, j);
            float bc = __shfl_sync(0xffffffffu, c,  j);
            float bd = __shfl_sync(0xffffffffu, dis_l, j);

            float x = bx + 1e-8f, y = by + 1e-8f, z = bz + 1e-8f;
            float dd = bd - off;
            float g0 = ex2f(C2 * dd * dd);
            float w  = g0 * bc;

            a0 = fmaf(z * z, w, a0);
            a1 = fmaf(y * z, w, a1);
            a2 = fmaf(y * y, w, a2);
            a3 = fmaf(x * z, w, a3);
            a4 = fmaf(x * y, w, a4);
            a5 = fmaf(x * x, w, a5);
        }
    }

    float f2 = a0 * a0;
    f2 = fmaf(2.0f * a1, a1, f2);
    f2 = fmaf(a2, a2, f2);
    f2 = fmaf(2.0f * a3, a3, f2);
    f2 = fmaf(2.0f * a4, a4, f2);
    f2 = fmaf(a5, a5, f2);

    float u = f2 + 1e-9f;
    float ss = u * u;
    #pragma unroll
    for (int o = 16; o > 0; o >>= 1)
        ss += __shfl_xor_sync(0xffffffffu, ss, o);
    float invn = __fdividef(1.0f, sqrtf(ss) + 1.0f);
    g_msgin[node * NB + lane] = f2 * invn;
}

// ---------------------------------------------------------------------------
// msg MLP: phase A fp32 (as before), phase B on tensor pipe (tf32 mma.sync).
// hid stored with HID_LD=132 stride for conflict-free fragment LDS.
__global__ __launch_bounds__(256, 3)
void msg_kernel7(const float* __restrict__ w1,
                 const float* __restrict__ b1,
                 const float* __restrict__ w2,
                 const float* __restrict__ b2,
                 float* __restrict__ out,
                 int nNodes)
{
    extern __shared__ float sm[];
    float* w1s = sm;                    // [32][128]  4096 floats
    float* mi  = w1s + NB * NA;         // [64][32]   2048 floats
    float* hid = mi + 64 * NB;          // [64][HID_LD] 8448 floats

    const int tid  = threadIdx.x;
    const int warp = tid >> 5;
    const int lane = tid & 31;
    const int node0 = blockIdx.x * 64;

    for (int i = tid; i < NB * NA / 4; i += 256)
        ((float4*)w1s)[i] = __ldg(&((const float4*)w1)[i]);
    for (int i = tid; i < 64 * NB / 4; i += 256) {
        int n = node0 + i / (NB / 4);
        float4 v = make_float4(0.f, 0.f, 0.f, 0.f);
        if (n < nNodes) v = ((const float4*)g_msgin)[(size_t)n * (NB / 4) + (i % (NB / 4))];
        ((float4*)mi)[i] = v;
    }
    __syncthreads();

    const int c4 = lane * 4;
    // ---- Phase A: hidden = silu(mi @ w1 + b1) (fp32) ----
    {
        float acc[8][4];
        #pragma unroll
        for (int i = 0; i < 8; i++)
            #pragma unroll
            for (int j = 0; j < 4; j++) acc[i][j] = 0.0f;

        const float* mrow = &mi[warp * 8 * NB];
        #pragma unroll
        for (int b = 0; b < NB; b += 4) {
            float4 wr0 = *(const float4*)(w1s + (b + 0) * NA + c4);
            float4 wr1 = *(const float4*)(w1s + (b + 1) * NA + c4);
            float4 wr2 = *(const float4*)(w1s + (b + 2) * NA + c4);
            float4 wr3 = *(const float4*)(w1s + (b + 3) * NA + c4);
            #pragma unroll
            for (int i = 0; i < 8; i++) {
                float4 f = *(const float4*)(mrow + i * NB + b);
                acc[i][0] = fmaf(f.x, wr0.x, acc[i][0]);
                acc[i][1] = fmaf(f.x, wr0.y, acc[i][1]);
                acc[i][2] = fmaf(f.x, wr0.z, acc[i][2]);
                acc[i][3] = fmaf(f.x, wr0.w, acc[i][3]);
                acc[i][0] = fmaf(f.y, wr1.x, acc[i][0]);
                acc[i][1] = fmaf(f.y, wr1.y, acc[i][1]);
                acc[i][2] = fmaf(f.y, wr1.z, acc[i][2]);
                acc[i][3] = fmaf(f.y, wr1.w, acc[i][3]);
                acc[i][0] = fmaf(f.z, wr2.x, acc[i][0]);
                acc[i][1] = fmaf(f.z, wr2.y, acc[i][1]);
                acc[i][2] = fmaf(f.z, wr2.z, acc[i][2]);
                acc[i][3] = fmaf(f.z, wr2.w, acc[i][3]);
                acc[i][0] = fmaf(f.w, wr3.x, acc[i][0]);
                acc[i][1] = fmaf(f.w, wr3.y, acc[i][1]);
                acc[i][2] = fmaf(f.w, wr3.z, acc[i][2]);
                acc[i][3] = fmaf(f.w, wr3.w, acc[i][3]);
            }
        }
        float4 b1v = __ldg((const float4*)(b1 + c4));
        #pragma unroll
        for (int i = 0; i < 8; i++) {
            float4 h;
            h.x = silu_tanh(acc[i][0] + b1v.x);
            h.y = silu_tanh(acc[i][1] + b1v.y);
            h.z = silu_tanh(acc[i][2] + b1v.z);
            h.w = silu_tanh(acc[i][3] + b1v.w);
            *(float4*)(hid + (warp * 8 + i) * HID_LD + c4) = h;
        }
    }
    __syncthreads();

    // ---- Phase B: out = hid @ w2 + b2 via m16n8k8 tf32 MMA ----
    // warp -> row-tile rt = warp&3 (rows rt*16..+15), col half = warp>>2 (64 cols, 8 n8-tiles)
    const int gr = lane >> 2;        // 0..7
    const int tc = lane & 3;         // 0..3
    const int rt = warp & 3;
    const int halfc = warp >> 2;
    const int rowbase = rt * 16;

    float d[8][4];
    #pragma unroll
    for (int j = 0; j < 8; j++)
        #pragma unroll
        for (int q = 0; q < 4; q++) d[j][q] = 0.0f;

    #pragma unroll 4
    for (int kk = 0; kk < 16; kk++) {
        const int k0 = kk * 8;
        const float* arow = hid + (rowbase + gr) * HID_LD + k0 + tc;
        uint32_t a0 = f2tf32(arow[0]);
        uint32_t a1 = f2tf32(arow[8 * HID_LD]);
        uint32_t a2 = f2tf32(arow[4]);
        uint32_t a3 = f2tf32(arow[8 * HID_LD + 4]);
        #pragma unroll
        for (int j = 0; j < 8; j++) {
            const int n0 = halfc * 64 + j * 8;
            const float* bp = w2 + (size_t)(k0 + tc) * NA + n0 + gr;
            uint32_t b0 = f2tf32(__ldg(bp));
            uint32_t b1 = f2tf32(__ldg(bp + 4 * NA));
            mma_tf32(d[j], a0, a1, a2, a3, b0, b1);
        }
    }

    // epilogue: add bias, store float2 pairs with row guards
    const int row0 = node0 + rowbase + gr;
    const int row1 = row0 + 8;
    #pragma unroll
    for (int j = 0; j < 8; j++) {
        const int col = halfc * 64 + j * 8 + 2 * tc;
        float2 bias = *(const float2*)(b2 + col);
        if (row0 < nNodes)
            *(float2*)(out + (size_t)row0 * NA + col) =
                make_float2(d[j][0] + bias.x, d[j][1] + bias.y);
        if (row1 < nNodes)
            *(float2*)(out + (size_t)row1 * NA + col) =
                make_float2(d[j][2] + bias.x, d[j][3] + bias.y);
    }
}

// ---------------------------------------------------------------------------
extern "C" void kernel_launch(void* const* d_in, const int* in_sizes, int n_in,
                              void* d_out, int out_size)
{
    const float* feat    = (const float*)d_in[0];
    const float* dis_vec = (const float*)d_in[1];
    const float* cj_w1   = (const float*)d_in[2];
    const float* cj_b1   = (const float*)d_in[3];
    const float* cj_w2   = (const float*)d_in[4];
    const float* cj_b2   = (const float*)d_in[5];
    const float* msg_w1  = (const float*)d_in[6];
    const float* msg_b1  = (const float*)d_in[7];
    const float* msg_w2  = (const float*)d_in[8];
    const float* msg_b2  = (const float*)d_in[9];
    const float* filt_w1 = (const float*)d_in[10];
    const float* filt_w2 = (const float*)d_in[11];
    const float* filt_b2 = (const float*)d_in[12];
    const int*   src     = (const int*)d_in[13];
    const int*   dst     = (const int*)d_in[14];

    const int nNodes = in_sizes[0] / NA;
    const int nEdges = in_sizes[1] / 3;

    float* out_msg  = (float*)d_out;
    float* out_filt = (float*)d_out + (size_t)nNodes * NA;

    const int msg_smem = (NB * NA + 64 * NB + 64 * HID_LD) * sizeof(float); // ~57 KB
    cudaFuncSetAttribute(msg_kernel7, cudaFuncAttributeMaxDynamicSharedMemorySize, msg_smem);

    // 1) cj MLP
    cj_kernel5<<<(nNodes + 31) / 32, 256>>>(feat, cj_w1, cj_b1, cj_w2, cj_b2, nNodes);

    // 2) windowed filt + scatter + staging (shared matvec broadcast)
    filt_scatter_kernel<<<(nEdges + 15) / 16, 256>>>(dis_vec, src, dst,
                                                     filt_w1, filt_w2, filt_b2,
                                                     out_filt, nEdges);

    // 3) gather (coalesced staged reads; resets g_deg)
    gather_kernel<<<(nNodes + 7) / 8, 256>>>(nNodes);

    // 4) msg MLP: phase A fp32, phase B tf32 tensor-core
    msg_kernel7<<<(nNodes + 63) / 64, 256, msg_smem>>>(msg_w1, msg_b1, msg_w2, msg_b2,
                                                       out_msg, nNodes);
}